// round 6
// baseline (speedup 1.0000x reference)
#include <cuda_runtime.h>

#define BB 2048
#define TT 1024
#define H  32
#define NA 4
#define CH 8
#define NCH (TT / CH)

typedef unsigned long long u64;

// packed f32x2 ops (sm_103a)
#define FMA2(d, a, b, c) \
    asm("fma.rn.f32x2 %0, %1, %2, %3;" : "=l"(d) : "l"(a), "l"(b), "l"(c))
#define ADD2(d, a, b) \
    asm("add.rn.f32x2 %0, %1, %2;" : "=l"(d) : "l"(a), "l"(b))

static __device__ __forceinline__ u64 f2u(float x, float y) {
    u64 r;
    asm("mov.b64 %0, {%1, %2};" : "=l"(r) : "f"(x), "f"(y));
    return r;
}
static __device__ __forceinline__ float2 u2f(u64 v) {
    float2 r;
    asm("mov.b64 {%0, %1}, %2;" : "=f"(r.x), "=f"(r.y) : "l"(v));
    return r;
}
static __device__ __forceinline__ float tanh_fast(float z) {
    float r;
    asm("tanh.approx.f32 %0, %1;" : "=f"(r) : "f"(z));
    return r;
}
// 64-bit butterfly shuffle (2x SHFL.32)
static __device__ __forceinline__ u64 bfly2(u64 v, int m) {
    unsigned lo, hi;
    asm("mov.b64 {%0, %1}, %2;" : "=r"(lo), "=r"(hi) : "l"(v));
    lo = __shfl_xor_sync(0xffffffffu, lo, m);
    hi = __shfl_xor_sync(0xffffffffu, hi, m);
    u64 r;
    asm("mov.b64 %0, {%1, %2};" : "=l"(r) : "r"(lo), "r"(hi));
    return r;
}

__global__ __launch_bounds__(32, 14) void vanilla_rnn_kernel(
    const float* __restrict__ act,   // [B, T, 4]
    const float* __restrict__ rew,   // [B, T, 1]
    const float* __restrict__ W_ih,  // [32, 5]
    const float* __restrict__ W_hh,  // [32, 32]
    const float* __restrict__ b_ih,  // [32]
    const float* __restrict__ b_hh,  // [32]
    const float* __restrict__ W_ro,  // [4, 32]
    const float* __restrict__ b_ro,  // [4]
    float* __restrict__ out)         // [B*T*4 logits][B*32 h_T]
{
    const int lane = threadIdx.x;
    const int b    = blockIdx.x;     // one batch row per warp/block
    const int q    = lane >> 3;      // j-quarter this lane accumulates
    const int lo   = lane & 7;

    // h ring: 8 slots; each row stores quarter q at float offset 12*q
    // (48B stride). Row stride 52 floats (208B). Both strides bank-checked
    // conflict-free for the quarter loads, the STS, and the readout reads.
    __shared__ __align__(16) float  ring[CH][52];
    __shared__ __align__(16) float  wro_s[NA][36];   // W_ro rows, padded
    __shared__ __align__(16) float4 xbuf[2][10];     // cp.async staging

    // W_hh: rows {lo, lo+8, lo+16, lo+24}, column-quarter q, packed j-pairs
    u64 w0[4], w1[4], w2[4], w3[4];
    {
        const u64* whh_u = (const u64*)W_hh;   // 16 packed pairs per row
        #pragma unroll
        for (int k = 0; k < 4; k++) {
            w0[k] = whh_u[(lo     ) * 16 + 4 * q + k];
            w1[k] = whh_u[(lo +  8) * 16 + 4 * q + k];
            w2[k] = whh_u[(lo + 16) * 16 + 4 * q + k];
            w3[k] = whh_u[(lo + 24) * 16 + 4 * q + k];
        }
    }

    float wip[5];
    #pragma unroll
    for (int k = 0; k < 5; k++) wip[k] = W_ih[lane * 5 + k];
    const float bias = b_ih[lane] + b_hh[lane];

    // readout mapping: lane -> (t_local = lane>>2, action = lane&3)
    const int a_act = lane & 3;
    const int tl    = lane >> 2;
    const float bro = b_ro[a_act];
    #pragma unroll
    for (int i = lane; i < NA * H; i += 32) wro_s[i >> 5][i & 31] = W_ro[i];

    ring[CH - 1][12 * q + lo] = 0.0f;    // h_{-1} = 0 (step 0 reads slot 7)

    const float4* actv = (const float4*)act + (size_t)b * TT;
    const float4* rewv = (const float4*)(rew + (size_t)b * TT);
    float* logits = out + (size_t)b * TT * NA;
    float* hT     = out + (size_t)BB * TT * NA + (size_t)b * H;

    // ---- prologue: chunk 0 inputs via plain loads, projected to registers
    float xc[CH];
    {
        float4 af[CH];
        #pragma unroll
        for (int i = 0; i < CH; i++) af[i] = __ldg(actv + i);
        const float4 r0 = __ldg(rewv + 0), r1 = __ldg(rewv + 1);
        const float rs[CH] = {r0.x, r0.y, r0.z, r0.w, r1.x, r1.y, r1.z, r1.w};
        #pragma unroll
        for (int i = 0; i < CH; i++)
            xc[i] = fmaf(af[i].x, wip[0], fmaf(af[i].y, wip[1],
                    fmaf(af[i].z, wip[2], fmaf(af[i].w, wip[3],
                    fmaf(rs[i], wip[4], bias)))));
    }

    float h = 0.0f;

    #pragma unroll 1
    for (int c = 0; c < NCH; c++) {
        // ---- prefetch chunk c+1 into smem staging
        const int cn = (c + 1 < NCH) ? (c + 1) : (NCH - 1);
        if (lane < 10) {
            const float4* src = (lane < 8) ? (actv + cn * CH + lane)
                                           : (rewv + cn * 2 + (lane - 8));
            unsigned sa = (unsigned)__cvta_generic_to_shared(&xbuf[c & 1][lane]);
            asm volatile("cp.async.ca.shared.global [%0], [%1], 16;"
                         :: "r"(sa), "l"(src));
        }
        asm volatile("cp.async.commit_group;" ::: "memory");

        // ---- 8 serial recurrence steps
        #pragma unroll
        for (int i = 0; i < CH; i++) {
            __syncwarp();   // previous step's STS visible (and WAR-safe)

            const float* prow = ring[(i + CH - 1) & (CH - 1)];
            // this lane's j-quarter, packed pairs: 2x LDS.128, conflict-free
            const ulonglong2 hA = *(const ulonglong2*)(prow + 12 * q);
            const ulonglong2 hB = *(const ulonglong2*)(prow + 12 * q + 4);

            // partial dots: 4 outputs x 8 j-values (4 FMA2 chains)
            u64 a0 = 0, a1 = 0, a2 = 0, a3 = 0;
            FMA2(a0, w0[0], hA.x, a0); FMA2(a0, w0[1], hA.y, a0);
            FMA2(a0, w0[2], hB.x, a0); FMA2(a0, w0[3], hB.y, a0);
            FMA2(a1, w1[0], hA.x, a1); FMA2(a1, w1[1], hA.y, a1);
            FMA2(a1, w1[2], hB.x, a1); FMA2(a1, w1[3], hB.y, a1);
            FMA2(a2, w2[0], hA.x, a2); FMA2(a2, w2[1], hA.y, a2);
            FMA2(a2, w2[2], hB.x, a2); FMA2(a2, w2[3], hB.y, a2);
            FMA2(a3, w3[0], hA.x, a3); FMA2(a3, w3[1], hA.y, a3);
            FMA2(a3, w3[2], hB.x, a3); FMA2(a3, w3[3], hB.y, a3);

            // horizontal sums -> packed partials for output pairs
            const float2 c0 = u2f(a0), c1 = u2f(a1);
            const float2 c2 = u2f(a2), c3 = u2f(a3);
            u64 P01 = f2u(c0.x + c0.y, c1.x + c1.y);  // (out lo,    lo+8 )
            u64 P23 = f2u(c2.x + c2.y, c3.x + c3.y);  // (out lo+16, lo+24)

            // butterfly reduction; output o lands at lane o
            u64 K = (q < 2) ? P01 : P23;
            u64 V = (q < 2) ? P23 : P01;
            u64 Vr = bfly2(V, 16);
            ADD2(K, K, Vr);
            u64 Kr = bfly2(K, 8);
            ADD2(K, K, Kr);
            const float2 S = u2f(K);
            const float s = (q & 1) ? S.y : S.x;   // this lane's output

            h = tanh_fast(s + xc[i]);
            ring[i][12 * q + lo] = h;   // conflict-free STS.32
        }
        __syncwarp();   // slot 7's STS visible before readout

        // ---- readout: 8 steps x 4 actions = 32 dots, 1 per lane
        {
            const float* hr = ring[tl];
            const ulonglong2* wp = (const ulonglong2*)wro_s[a_act];
            u64 a0 = 0, a1 = 0, a2 = 0, a3 = 0;
            #pragma unroll
            for (int k = 0; k < 8; k++) {
                // chunk k = j in [4k, 4k+4): quarter k>>1, half k&1
                const ulonglong2 hq =
                    *(const ulonglong2*)(hr + 12 * (k >> 1) + 4 * (k & 1));
                const ulonglong2 wq = wp[k];
                if (k & 1) {
                    FMA2(a2, wq.x, hq.x, a2);
                    FMA2(a3, wq.y, hq.y, a3);
                } else {
                    FMA2(a0, wq.x, hq.x, a0);
                    FMA2(a1, wq.y, hq.y, a1);
                }
            }
            ADD2(a0, a0, a1);
            ADD2(a2, a2, a3);
            ADD2(a0, a0, a2);
            const float2 d = u2f(a0);
            // (c*8 + tl)*4 + a_act == c*32 + lane -> coalesced 128B store
            logits[(size_t)c * 32 + lane] = d.x + d.y + bro;
        }

        // ---- project chunk c+1 (cp.async has had 8 steps of slack)
        {
            asm volatile("cp.async.wait_group 0;" ::: "memory");
            __syncwarp();
            const float4* xb = &xbuf[c & 1][0];
            const float4 r0 = xb[8], r1 = xb[9];
            const float rs[CH] = {r0.x, r0.y, r0.z, r0.w,
                                  r1.x, r1.y, r1.z, r1.w};
            #pragma unroll
            for (int i = 0; i < CH; i++) {
                const float4 af = xb[i];
                xc[i] = fmaf(af.x, wip[0], fmaf(af.y, wip[1],
                        fmaf(af.z, wip[2], fmaf(af.w, wip[3],
                        fmaf(rs[i], wip[4], bias)))));
            }
        }
    }

    // final hidden state: lane holds h[lane] from t = 1023
    hT[lane] = h;
}

extern "C" void kernel_launch(void* const* d_in, const int* in_sizes, int n_in,
                              void* d_out, int out_size) {
    const float* act  = (const float*)d_in[0];
    const float* rew  = (const float*)d_in[1];
    const float* W_ih = (const float*)d_in[2];
    const float* W_hh = (const float*)d_in[3];
    const float* b_ih = (const float*)d_in[4];
    const float* b_hh = (const float*)d_in[5];
    const float* W_ro = (const float*)d_in[6];
    const float* b_ro = (const float*)d_in[7];
    float* out = (float*)d_out;

    vanilla_rnn_kernel<<<BB, 32>>>(act, rew, W_ih, W_hh, b_ih, b_hh,
                                   W_ro, b_ro, out);
}

// round 7
// speedup vs baseline: 1.0230x; 1.0230x over previous
#include <cuda_runtime.h>

#define BB 2048
#define TT 1024
#define H  32
#define NA 4
#define CH 8
#define NCH (TT / CH)

typedef unsigned long long u64;

// packed f32x2 ops (sm_103a)
#define FMA2(d, a, b, c) \
    asm("fma.rn.f32x2 %0, %1, %2, %3;" : "=l"(d) : "l"(a), "l"(b), "l"(c))
#define ADD2(d, a, b) \
    asm("add.rn.f32x2 %0, %1, %2;" : "=l"(d) : "l"(a), "l"(b))

static __device__ __forceinline__ u64 f2u(float x, float y) {
    u64 r;
    asm("mov.b64 %0, {%1, %2};" : "=l"(r) : "f"(x), "f"(y));
    return r;
}
static __device__ __forceinline__ float2 u2f(u64 v) {
    float2 r;
    asm("mov.b64 {%0, %1}, %2;" : "=f"(r.x), "=f"(r.y) : "l"(v));
    return r;
}
static __device__ __forceinline__ float tanh_fast(float z) {
    float r;
    asm("tanh.approx.f32 %0, %1;" : "=f"(r) : "f"(z));
    return r;
}
// 64-bit butterfly shuffle (2x SHFL.32, parallel)
static __device__ __forceinline__ u64 bfly2(u64 v, int m) {
    unsigned lo, hi;
    asm("mov.b64 {%0, %1}, %2;" : "=r"(lo), "=r"(hi) : "l"(v));
    lo = __shfl_xor_sync(0xffffffffu, lo, m);
    hi = __shfl_xor_sync(0xffffffffu, hi, m);
    u64 r;
    asm("mov.b64 %0, {%1, %2};" : "=l"(r) : "r"(lo), "r"(hi));
    return r;
}

__global__ __launch_bounds__(32, 14) void vanilla_rnn_kernel(
    const float* __restrict__ act,   // [B, T, 4]
    const float* __restrict__ rew,   // [B, T, 1]
    const float* __restrict__ W_ih,  // [32, 5]
    const float* __restrict__ W_hh,  // [32, 32]
    const float* __restrict__ b_ih,  // [32]
    const float* __restrict__ b_hh,  // [32]
    const float* __restrict__ W_ro,  // [4, 32]
    const float* __restrict__ b_ro,  // [4]
    float* __restrict__ out)         // [B*T*4 logits][B*32 h_T]
{
    const int lane = threadIdx.x;
    const int b    = blockIdx.x;     // one batch row per warp/block
    const int f    = lane >> 4;      // j-half this lane accumulates
    const int p    = lane & 15;      // output pair (2p, 2p+1)

    __shared__ __align__(16) float  ring[CH][36];    // h history, padded rows
    __shared__ __align__(16) float  wro_s[NA][36];   // W_ro rows, padded
    __shared__ __align__(16) float4 xbuf[2][10];     // cp.async staging

    // W_hh rows 2p, 2p+1, column-half f, packed j-pairs (8 each)
    u64 wa[8], wb[8];
    {
        const u64* whh_u = (const u64*)W_hh;   // 16 packed pairs per row
        #pragma unroll
        for (int k = 0; k < 8; k++) {
            wa[k] = whh_u[(2 * p)     * 16 + 8 * f + k];
            wb[k] = whh_u[(2 * p + 1) * 16 + 8 * f + k];
        }
    }

    // input projection for outputs 2p, 2p+1 packed: wip[k] = (W_ih[2p][k], W_ih[2p+1][k])
    u64 wip[5];
    #pragma unroll
    for (int k = 0; k < 5; k++)
        wip[k] = f2u(W_ih[2 * p * 5 + k], W_ih[(2 * p + 1) * 5 + k]);
    const u64 biasp = f2u(b_ih[2 * p] + b_hh[2 * p],
                          b_ih[2 * p + 1] + b_hh[2 * p + 1]);

    // readout mapping: lane -> (t_local = lane>>2, action = lane&3)
    const int a_act = lane & 3;
    const int tl    = lane >> 2;
    const float bro = b_ro[a_act];
    #pragma unroll
    for (int i = lane; i < NA * H; i += 32) wro_s[i >> 5][i & 31] = W_ro[i];

    if (f == 0) *(u64*)&ring[CH - 1][2 * p] = 0ull;  // h_{-1} = 0 (slot 7)

    const float4* actv = (const float4*)act + (size_t)b * TT;
    const float4* rewv = (const float4*)(rew + (size_t)b * TT);
    float* logits = out + (size_t)b * TT * NA;
    float* hT     = out + (size_t)BB * TT * NA + (size_t)b * H;

    // ---- prologue: chunk 0 inputs via plain loads, packed projection
    u64 xcp[CH];
    {
        float4 af[CH];
        #pragma unroll
        for (int i = 0; i < CH; i++) af[i] = __ldg(actv + i);
        const float4 r0 = __ldg(rewv + 0), r1 = __ldg(rewv + 1);
        const float rs[CH] = {r0.x, r0.y, r0.z, r0.w, r1.x, r1.y, r1.z, r1.w};
        #pragma unroll
        for (int i = 0; i < CH; i++) {
            u64 t = biasp;
            FMA2(t, f2u(rs[i],    rs[i]),    wip[4], t);
            FMA2(t, f2u(af[i].w,  af[i].w),  wip[3], t);
            FMA2(t, f2u(af[i].z,  af[i].z),  wip[2], t);
            FMA2(t, f2u(af[i].y,  af[i].y),  wip[1], t);
            FMA2(t, f2u(af[i].x,  af[i].x),  wip[0], t);
            xcp[i] = t;
        }
    }

    #pragma unroll 1
    for (int c = 0; c < NCH; c++) {
        // ---- prefetch chunk c+1 into smem staging
        const int cn = (c + 1 < NCH) ? (c + 1) : (NCH - 1);
        if (lane < 10) {
            const float4* src = (lane < 8) ? (actv + cn * CH + lane)
                                           : (rewv + cn * 2 + (lane - 8));
            unsigned sa = (unsigned)__cvta_generic_to_shared(&xbuf[c & 1][lane]);
            asm volatile("cp.async.ca.shared.global [%0], [%1], 16;"
                         :: "r"(sa), "l"(src));
        }
        asm volatile("cp.async.commit_group;" ::: "memory");

        // ---- 8 serial recurrence steps
        #pragma unroll
        for (int i = 0; i < CH; i++) {
            __syncwarp();   // previous step's STS visible

            // this lane's j-half of h_{t-1}: 4x LDS.128 (2 distinct addrs)
            const ulonglong2* hp =
                (const ulonglong2*)(ring[(i + CH - 1) & (CH - 1)] + 16 * f);
            const ulonglong2 q0 = hp[0], q1 = hp[1], q2 = hp[2], q3 = hp[3];

            // partials for outputs (2p, 2p+1) over 16 j-values
            u64 a0 = 0, a1 = 0, b0 = 0, b1 = 0;
            FMA2(a0, wa[0], q0.x, a0); FMA2(a0, wa[1], q0.y, a0);
            FMA2(a0, wa[2], q1.x, a0); FMA2(a0, wa[3], q1.y, a0);
            FMA2(a1, wa[4], q2.x, a1); FMA2(a1, wa[5], q2.y, a1);
            FMA2(a1, wa[6], q3.x, a1); FMA2(a1, wa[7], q3.y, a1);
            FMA2(b0, wb[0], q0.x, b0); FMA2(b0, wb[1], q0.y, b0);
            FMA2(b0, wb[2], q1.x, b0); FMA2(b0, wb[3], q1.y, b0);
            FMA2(b1, wb[4], q2.x, b1); FMA2(b1, wb[5], q2.y, b1);
            FMA2(b1, wb[6], q3.x, b1); FMA2(b1, wb[7], q3.y, b1);
            ADD2(a0, a0, a1);
            ADD2(b0, b0, b1);
            const float2 ca = u2f(a0), cb = u2f(b0);
            u64 P = f2u(ca.x + ca.y, cb.x + cb.y);  // (d_2p, d_2p+1) half f

            // one butterfly round completes both dots on every lane
            const u64 Pr = bfly2(P, 16);
            ADD2(P, P, Pr);
            ADD2(P, P, xcp[i]);          // + input projection (packed)

            const float2 D = u2f(P);
            const float h0 = tanh_fast(D.x);   // parallel MUFUs
            const float h1 = tanh_fast(D.y);

            if (f == 0)                         // 16 lanes write 128B, no conflicts
                *(u64*)&ring[i][2 * p] = f2u(h0, h1);
        }
        __syncwarp();   // slot 7's STS visible before readout

        // ---- readout: 8 steps x 4 actions = 32 dots, 1 per lane
        {
            const ulonglong2* hp = (const ulonglong2*)ring[tl];
            const ulonglong2* wp = (const ulonglong2*)wro_s[a_act];
            u64 a0 = 0, a1 = 0, a2 = 0, a3 = 0;
            #pragma unroll
            for (int j = 0; j < 4; j++) {
                ulonglong2 hq1 = hp[2 * j], hq2 = hp[2 * j + 1];
                ulonglong2 wq1 = wp[2 * j], wq2 = wp[2 * j + 1];
                FMA2(a0, wq1.x, hq1.x, a0);
                FMA2(a1, wq1.y, hq1.y, a1);
                FMA2(a2, wq2.x, hq2.x, a2);
                FMA2(a3, wq2.y, hq2.y, a3);
            }
            ADD2(a0, a0, a1);
            ADD2(a2, a2, a3);
            ADD2(a0, a0, a2);
            const float2 d = u2f(a0);
            // (c*8 + tl)*4 + a_act == c*32 + lane -> coalesced 128B store
            logits[(size_t)c * 32 + lane] = d.x + d.y + bro;
        }

        // ---- project chunk c+1 (cp.async has had 8 steps of slack)
        {
            asm volatile("cp.async.wait_group 0;" ::: "memory");
            __syncwarp();
            const float4* xb = &xbuf[c & 1][0];
            const float4 r0 = xb[8], r1 = xb[9];
            const float rs[CH] = {r0.x, r0.y, r0.z, r0.w,
                                  r1.x, r1.y, r1.z, r1.w};
            #pragma unroll
            for (int i = 0; i < CH; i++) {
                const float4 af = xb[i];
                u64 t = biasp;
                FMA2(t, f2u(rs[i],  rs[i]),  wip[4], t);
                FMA2(t, f2u(af.w,   af.w),   wip[3], t);
                FMA2(t, f2u(af.z,   af.z),   wip[2], t);
                FMA2(t, f2u(af.y,   af.y),   wip[1], t);
                FMA2(t, f2u(af.x,   af.x),   wip[0], t);
                xcp[i] = t;
            }
        }
    }

    // final hidden state h_T = ring slot 7 (step t=1023)
    hT[lane] = ring[CH - 1][lane];
}

extern "C" void kernel_launch(void* const* d_in, const int* in_sizes, int n_in,
                              void* d_out, int out_size) {
    const float* act  = (const float*)d_in[0];
    const float* rew  = (const float*)d_in[1];
    const float* W_ih = (const float*)d_in[2];
    const float* W_hh = (const float*)d_in[3];
    const float* b_ih = (const float*)d_in[4];
    const float* b_hh = (const float*)d_in[5];
    const float* W_ro = (const float*)d_in[6];
    const float* b_ro = (const float*)d_in[7];
    float* out = (float*)d_out;

    vanilla_rnn_kernel<<<BB, 32>>>(act, rew, W_ih, W_hh, b_ih, b_hh,
                                   W_ro, b_ro, out);
}